// round 2
// baseline (speedup 1.0000x reference)
#include <cuda_runtime.h>
#include <cstdint>

#define IMG_H 320
#define IMG_W 960
#define IMG_HW (IMG_H * IMG_W)
#define MAXD 128
#define W4 (IMG_W / 4)
#define DSEG 32

// ---------------- scratch (no allocation allowed) ----------------
__device__ float g_yL[IMG_HW];
__device__ float g_yR[IMG_HW];
__device__ float g_cbL[IMG_HW];
__device__ float g_cbR[IMG_HW];
__device__ float g_crL[IMG_HW];
__device__ float g_crR[IMG_HW];
__device__ int   g_cenL[IMG_HW];
__device__ int   g_cenR[IMG_HW];

// ---------------- kernel 1: RGB -> YCbCr for both images ----------------
__global__ void ycbcr_kernel(const float* __restrict__ left,
                             const float* __restrict__ right) {
    int i = blockIdx.x * blockDim.x + threadIdx.x;
    if (i >= IMG_HW) return;

    {
        float r = left[i];
        float g = left[IMG_HW + i];
        float b = left[2 * IMG_HW + i];
        float y = 0.299f * r + 0.587f * g + 0.114f * b;
        g_yL[i]  = y;
        g_cbL[i] = (b - y) * 0.564f + 0.5f;
        g_crL[i] = (r - y) * 0.713f + 0.5f;
    }
    {
        float r = right[i];
        float g = right[IMG_HW + i];
        float b = right[2 * IMG_HW + i];
        float y = 0.299f * r + 0.587f * g + 0.114f * b;
        g_yR[i]  = y;
        g_cbR[i] = (b - y) * 0.564f + 0.5f;
        g_crR[i] = (r - y) * 0.713f + 0.5f;
    }
}

// ---------------- kernel 2: 24-bit census (5x5, skip (v=1,u=1)) ----------------
__device__ __forceinline__ int census_at(const float* __restrict__ Y, int yy, int xx) {
    // border pixels (pad of 2) are zero
    if (yy < 2 || yy >= IMG_H - 2 || xx < 2 || xx >= IMG_W - 2) return 0;
    float c = Y[yy * IMG_W + xx];
    int cen = 0;
#pragma unroll
    for (int v = 0; v < 5; v++) {
#pragma unroll
        for (int u = 0; u < 5; u++) {
            if (u == 1 && v == 1) continue;
            float nb = Y[(yy + v - 2) * IMG_W + (xx + u - 2)];
            cen = cen * 2 + (nb >= c ? 1 : 0);
        }
    }
    return cen;
}

__global__ void census_kernel() {
    int i = blockIdx.x * blockDim.x + threadIdx.x;
    if (i >= IMG_HW) return;
    int yy = i / IMG_W;
    int xx = i - yy * IMG_W;
    g_cenL[i] = census_at(g_yL, yy, xx);
    g_cenR[i] = census_at(g_yR, yy, xx);
}

// ---------------- kernel 3: cost volume ----------------
// out layout: [384, H, W]  (0..127 hamming, 128..255 |cb|, 256..383 |cr|)
// Each thread: 4 consecutive x, DSEG consecutive disparities (blockIdx.y segment).
__global__ void cost_kernel(float* __restrict__ out) {
    int t = blockIdx.x * blockDim.x + threadIdx.x;
    if (t >= IMG_H * W4) return;
    int yy = t / W4;
    int x  = (t - yy * W4) * 4;
    int d0 = blockIdx.y * DSEG;
    int rowo = yy * IMG_W;

    // right-side values (fixed for this thread)
    int   rcen[4];
    float rcb[4], rcr[4];
#pragma unroll
    for (int i = 0; i < 4; i++) {
        rcen[i] = g_cenR[rowo + x + i];
        rcb[i]  = g_cbR[rowo + x + i];
        rcr[i]  = g_crR[rowo + x + i];
    }

    // left rolling window at x + d0 + i (clamped; invalid lanes masked anyway)
    int   lcen[4];
    float lcb[4], lcr[4];
#pragma unroll
    for (int i = 0; i < 4; i++) {
        int xi = min(x + d0 + i, IMG_W - 1);
        lcen[i] = g_cenL[rowo + xi];
        lcb[i]  = g_cbL[rowo + xi];
        lcr[i]  = g_crL[rowo + xi];
    }

    for (int dd = 0; dd < DSEG; dd++) {
        int d = d0 + dd;
        float hvv[4], cbb[4], crr[4];
#pragma unroll
        for (int i = 0; i < 4; i++) {
            bool valid = (x + i + d) < IMG_W;
            hvv[i] = valid ? (float)__popc(lcen[i] ^ rcen[i]) : 0.0f;
            cbb[i] = valid ? fabsf(lcb[i] - rcb[i]) : 0.0f;
            crr[i] = valid ? fabsf(lcr[i] - rcr[i]) : 0.0f;
        }
        float4 hv  = make_float4(hvv[0], hvv[1], hvv[2], hvv[3]);
        float4 cbv = make_float4(cbb[0], cbb[1], cbb[2], cbb[3]);
        float4 crv = make_float4(crr[0], crr[1], crr[2], crr[3]);

        int base = rowo + x;
        *(float4*)(out + (size_t)d * IMG_HW + base)              = hv;
        *(float4*)(out + (size_t)(MAXD + d) * IMG_HW + base)     = cbv;
        *(float4*)(out + (size_t)(2 * MAXD + d) * IMG_HW + base) = crv;

        // slide left window by one
#pragma unroll
        for (int i = 0; i < 3; i++) {
            lcen[i] = lcen[i + 1];
            lcb[i]  = lcb[i + 1];
            lcr[i]  = lcr[i + 1];
        }
        int xn = min(x + d + 4, IMG_W - 1);
        lcen[3] = g_cenL[rowo + xn];
        lcb[3]  = g_cbL[rowo + xn];
        lcr[3]  = g_crL[rowo + xn];
    }
}

// ---------------- launch ----------------
extern "C" void kernel_launch(void* const* d_in, const int* in_sizes, int n_in,
                              void* d_out, int out_size) {
    const float* left  = (const float*)d_in[0];
    const float* right = (const float*)d_in[1];
    // d_in[2] is maxdisp (always 128 for this problem's shapes)
    float* out = (float*)d_out;

    {
        int threads = 256;
        int blocks = (IMG_HW + threads - 1) / threads;
        ycbcr_kernel<<<blocks, threads>>>(left, right);
        census_kernel<<<blocks, threads>>>();
    }
    {
        int threads = 256;
        int nthr = IMG_H * W4;                 // 76800
        dim3 grid((nthr + threads - 1) / threads, MAXD / DSEG);  // (300, 4)
        cost_kernel<<<grid, threads>>>(out);
    }
}

// round 4
// speedup vs baseline: 1.1974x; 1.1974x over previous
#include <cuda_runtime.h>
#include <cstdint>

#define IMG_H 320
#define IMG_W 960
#define IMG_HW (IMG_H * IMG_W)
#define MAXD 128
#define W4 (IMG_W / 4)
#define DSEG 32

// fused-tile geometry
#define TLW 64
#define TLH 4
#define SMW (TLW + 4)   // 68
#define SMH (TLH + 4)   // 8

// ---------------- scratch (no allocation allowed) ----------------
__device__ float g_cbL[IMG_HW];
__device__ float g_cbR[IMG_HW];
__device__ float g_crL[IMG_HW];
__device__ float g_crR[IMG_HW];
__device__ int   g_cenL[IMG_HW];
__device__ int   g_cenR[IMG_HW];

__device__ __forceinline__ float luma(float r, float g, float b) {
    return 0.299f * r + 0.587f * g + 0.114f * b;
}

// ---------------- kernel 1: fused RGB->YCbCr + census ----------------
// Y is never written to global: computed into smem (with 2-px halo), census
// read from smem. Only cb, cr, census go to global scratch.
__global__ void __launch_bounds__(256) prep_kernel(const float* __restrict__ left,
                                                   const float* __restrict__ right) {
    __shared__ float ytL[SMH][SMW];
    __shared__ float ytR[SMH][SMW];

    const int tid = threadIdx.x;
    const int tx0 = (blockIdx.x % (IMG_W / TLW)) * TLW;
    const int ty0 = (blockIdx.x / (IMG_W / TLW)) * TLH;

    // phase 1: fill Y tile + halo for both images (clamped reads; clamped
    // values only feed census of border pixels, which are forced to 0)
    for (int s = tid; s < SMH * SMW; s += 256) {
        int ly = s / SMW, lx = s % SMW;
        int gy = ty0 + ly - 2; gy = max(0, min(gy, IMG_H - 1));
        int gx = tx0 + lx - 2; gx = max(0, min(gx, IMG_W - 1));
        int gi = gy * IMG_W + gx;
        ytL[ly][lx] = luma(left[gi],  left[IMG_HW + gi],  left[2 * IMG_HW + gi]);
        ytR[ly][lx] = luma(right[gi], right[IMG_HW + gi], right[2 * IMG_HW + gi]);
    }
    __syncthreads();

    // phase 2: each thread owns one tile pixel
    const int ly = tid / TLW, lx = tid % TLW;
    const int gy = ty0 + ly, gx = tx0 + lx;
    const int gi = gy * IMG_W + gx;
    const bool interior = (gy >= 2) && (gy < IMG_H - 2) && (gx >= 2) && (gx < IMG_W - 2);

    int cenL = 0, cenR = 0;
    {
        float cL = ytL[ly + 2][lx + 2];
        float cR = ytR[ly + 2][lx + 2];
#pragma unroll
        for (int v = 0; v < 5; v++) {
#pragma unroll
            for (int u = 0; u < 5; u++) {
                if (u == 1 && v == 1) continue;
                cenL = cenL * 2 + (ytL[ly + v][lx + u] >= cL ? 1 : 0);
                cenR = cenR * 2 + (ytR[ly + v][lx + u] >= cR ? 1 : 0);
            }
        }
    }
    g_cenL[gi] = interior ? cenL : 0;
    g_cenR[gi] = interior ? cenR : 0;

    {
        float r = left[gi], b = left[2 * IMG_HW + gi];
        float y = ytL[ly + 2][lx + 2];
        g_cbL[gi] = (b - y) * 0.564f + 0.5f;
        g_crL[gi] = (r - y) * 0.713f + 0.5f;
    }
    {
        float r = right[gi], b = right[2 * IMG_HW + gi];
        float y = ytR[ly + 2][lx + 2];
        g_cbR[gi] = (b - y) * 0.564f + 0.5f;
        g_crR[gi] = (r - y) * 0.713f + 0.5f;
    }
}

// ---------------- kernel 2: cost volume ----------------
// out layout: [384, H, W]  (0..127 hamming, 128..255 |cb|, 256..383 |cr|)
// Each thread: 4 consecutive x, DSEG consecutive disparities (blockIdx.y).
__global__ void __launch_bounds__(256) cost_kernel(float* __restrict__ out) {
    int t = blockIdx.x * blockDim.x + threadIdx.x;
    if (t >= IMG_H * W4) return;
    int yy = t / W4;
    int x  = (t - yy * W4) * 4;
    int d0 = blockIdx.y * DSEG;
    int rowo = yy * IMG_W;

    // right-side values (fixed for this thread)
    int   rcen[4];
    float rcb[4], rcr[4];
#pragma unroll
    for (int i = 0; i < 4; i++) {
        rcen[i] = g_cenR[rowo + x + i];
        rcb[i]  = g_cbR[rowo + x + i];
        rcr[i]  = g_crR[rowo + x + i];
    }

    // left rolling window at x + d0 + i (clamped; invalid lanes masked anyway)
    int   lcen[4];
    float lcb[4], lcr[4];
#pragma unroll
    for (int i = 0; i < 4; i++) {
        int xi = min(x + d0 + i, IMG_W - 1);
        lcen[i] = g_cenL[rowo + xi];
        lcb[i]  = g_cbL[rowo + xi];
        lcr[i]  = g_crL[rowo + xi];
    }

#pragma unroll 4
    for (int dd = 0; dd < DSEG; dd++) {
        int d = d0 + dd;
        float hvv[4], cbb[4], crr[4];
#pragma unroll
        for (int i = 0; i < 4; i++) {
            bool valid = (x + i + d) < IMG_W;
            hvv[i] = valid ? (float)__popc(lcen[i] ^ rcen[i]) : 0.0f;
            cbb[i] = valid ? fabsf(lcb[i] - rcb[i]) : 0.0f;
            crr[i] = valid ? fabsf(lcr[i] - rcr[i]) : 0.0f;
        }
        float4 hv  = make_float4(hvv[0], hvv[1], hvv[2], hvv[3]);
        float4 cbv = make_float4(cbb[0], cbb[1], cbb[2], cbb[3]);
        float4 crv = make_float4(crr[0], crr[1], crr[2], crr[3]);

        int base = rowo + x;
        __stcs((float4*)(out + (size_t)d * IMG_HW + base), hv);
        __stcs((float4*)(out + (size_t)(MAXD + d) * IMG_HW + base), cbv);
        __stcs((float4*)(out + (size_t)(2 * MAXD + d) * IMG_HW + base), crv);

        // slide left window by one
#pragma unroll
        for (int i = 0; i < 3; i++) {
            lcen[i] = lcen[i + 1];
            lcb[i]  = lcb[i + 1];
            lcr[i]  = lcr[i + 1];
        }
        int xn = min(x + d + 4, IMG_W - 1);
        lcen[3] = g_cenL[rowo + xn];
        lcb[3]  = g_cbL[rowo + xn];
        lcr[3]  = g_crL[rowo + xn];
    }
}

// ---------------- launch ----------------
extern "C" void kernel_launch(void* const* d_in, const int* in_sizes, int n_in,
                              void* d_out, int out_size) {
    const float* left  = (const float*)d_in[0];
    const float* right = (const float*)d_in[1];
    float* out = (float*)d_out;

    {
        int blocks = (IMG_W / TLW) * (IMG_H / TLH);   // 15 * 80 = 1200
        prep_kernel<<<blocks, 256>>>(left, right);
    }
    {
        int threads = 256;
        int nthr = IMG_H * W4;                         // 76800
        dim3 grid((nthr + threads - 1) / threads, MAXD / DSEG);  // (300, 4)
        cost_kernel<<<grid, threads>>>(out);
    }
}